// round 4
// baseline (speedup 1.0000x reference)
#include <cuda_runtime.h>
#include <cuda_bf16.h>
#include <cstdint>

// ---------------- packed bf16 hi/lo intermediate buffers (u32 planes) --------
__device__ __align__(16) unsigned g_l0 [8 * 256 * 64 * 64];
__device__ __align__(16) unsigned g_l1 [8 * 256 * 32 * 32];
__device__ __align__(16) unsigned g_l2 [8 * 256 * 16 * 16];
__device__ __align__(16) unsigned g_f  [8 * 256 * 64 * 64];
__device__ __align__(16) unsigned g_t1c[8 * 256 * 64 * 64];
__device__ __align__(16) unsigned g_t1r[8 * 256 * 64 * 64];
__device__ __align__(16) unsigned g_t2c[8 * 256 * 64 * 64];
__device__ __align__(16) unsigned g_t2r[8 * 256 * 64 * 64];

// ---------------- bf16 hi/lo weight arena (t-major K layout) -----------------
#define WOFF_L0  0LL
#define WOFF_L1  131072LL
#define WOFF_L2  393216LL
#define WOFF_FW0 917504LL
#define WOFF_FW1 1507328LL
#define WOFF_FW2 2097152LL
#define WOFF_CW0 2686976LL
#define WOFF_CW1 3276800LL
#define WOFF_CW2 3866624LL
#define WOFF_RW0 4456448LL
#define WOFF_RW1 5046272LL
#define WOFF_RW2 5636096LL
#define WARENA   5672960LL
__device__ __nv_bfloat16 g_whi[WARENA];
__device__ __nv_bfloat16 g_wlo[WARENA];

// ---------------- helpers ----------------------------------------------------
#define SWZ(off)  ((off) ^ (((off) >> 3) & 0x70))   // 128B-row swizzle
#define SWZA(off) ((off) ^ (((off) >> 4) & 0x70))   // 256B-row swizzle

static __device__ __forceinline__ uint32_t smem_u32(const void* p) {
    uint32_t a;
    asm("{ .reg .u64 t; cvta.to.shared.u64 t, %1; cvt.u32.u64 %0, t; }"
        : "=r"(a) : "l"(p));
    return a;
}
static __device__ __forceinline__ uint32_t packf(float v) {
    uint32_t vb = __float_as_uint(v);
    uint32_t hb = (vb + 0x7FFFu + ((vb >> 16) & 1u)) & 0xFFFF0000u;
    float r = v - __uint_as_float(hb);
    uint32_t rb = __float_as_uint(r);
    uint32_t lb = (rb + 0x7FFFu + ((rb >> 16) & 1u)) & 0xFFFF0000u;
    return (hb >> 16) | lb;
}
static __device__ __forceinline__ float unpackf(uint32_t p) {
    return __uint_as_float(p << 16) + __uint_as_float(p & 0xFFFF0000u);
}

#define LDSM_X4(r0, r1, r2, r3, ad) \
    asm volatile("ldmatrix.sync.aligned.m8n8.x4.shared.b16 {%0,%1,%2,%3}, [%4];" \
                 : "=r"(r0), "=r"(r1), "=r"(r2), "=r"(r3) : "r"(ad))
#define LDSM_X4T(r0, r1, r2, r3, ad) \
    asm volatile("ldmatrix.sync.aligned.m8n8.x4.trans.shared.b16 {%0,%1,%2,%3}, [%4];" \
                 : "=r"(r0), "=r"(r1), "=r"(r2), "=r"(r3) : "r"(ad))
#define LDSM_X2(r0, r1, ad) \
    asm volatile("ldmatrix.sync.aligned.m8n8.x2.shared.b16 {%0,%1}, [%2];" \
                 : "=r"(r0), "=r"(r1) : "r"(ad))
#define MMA16816(d, a, b) \
    asm volatile("mma.sync.aligned.m16n8k16.row.col.f32.bf16.bf16.f32 " \
                 "{%0,%1,%2,%3},{%4,%5,%6,%7},{%8,%9},{%0,%1,%2,%3};" \
                 : "+f"((d)[0]), "+f"((d)[1]), "+f"((d)[2]), "+f"((d)[3]) \
                 : "r"((a)[0]), "r"((a)[1]), "r"((a)[2]), "r"((a)[3]), \
                   "r"((b)[0]), "r"((b)[1]))
#define CVT2BF(dst, hi, lo) \
    asm("cvt.rn.bf16x2.f32 %0, %1, %2;" : "=r"(dst) : "f"(hi), "f"(lo))

// ---------------- merged weight pre-transform --------------------------------
struct WtEnt { const float* src; long long start; long long n; int coutA; int cin; int taps; };
struct WtTab { WtEnt e[12]; };

__global__ void wt_all(WtTab T, __nv_bfloat16* __restrict__ hi,
                       __nv_bfloat16* __restrict__ lo)
{
    long long idx = (long long)blockIdx.x * 256 + threadIdx.x;
    if (idx >= WARENA) return;
    int i = 0;
#pragma unroll
    for (int j = 1; j < 12; ++j) if (idx >= T.e[j].start) i = j;
    const WtEnt E = T.e[i];
    long long local = idx - E.start;
    const int Kk = E.cin * E.taps;
    long long co = local / Kk;
    int r  = (int)(local - co * Kk);
    int t  = r / E.cin;
    int ci = r - t * E.cin;
    float v = 0.f;
    if (co < E.coutA) v = E.src[co * Kk + (long long)ci * E.taps + t];
    __nv_bfloat16 h = __float2bfloat16(v);
    float rr = v - __bfloat162float(h);
    hi[idx] = h;
    lo[idx] = __float2bfloat16(rr);
}

// ---------------- implicit-GEMM conv via mma.sync bf16 (3-term split) --------
struct GArgs {
    const void* in;
    const __nv_bfloat16* wh;
    const __nv_bfloat16* wl;
    const float* bias;
    void* out;
};

template <int NTILE, bool RELU, bool INP, bool OUTP>
__global__ void __launch_bounds__(256, 2)
gemm_conv(GArgs A1, GArgs A2, int nyPer,
          int Cin, int CoutActual, int K, int taps, int H, int Wd,
          long long ob, long long oc, long long op)
{
    extern __shared__ char dsm[];
    const int tid = threadIdx.x;

    uint32_t u0  = smem_u32(dsm);
    uint32_t pad = (1024u - (u0 & 1023u)) & 1023u;
    char*    db  = dsm + pad;
    uint32_t dyn = u0 + pad;

    const int yb  = blockIdx.y;
    const int sel = (yb >= nyPer) ? 1 : 0;
    const int coTile = sel ? (yb - nyPer) : yb;

    const void* inv            = sel ? A2.in   : A1.in;
    const __nv_bfloat16* whi   = sel ? A2.wh   : A1.wh;
    const __nv_bfloat16* wlo   = sel ? A2.wl   : A1.wl;
    const float* bias          = sel ? A2.bias : A1.bias;
    void* outv                 = sel ? A2.out  : A1.out;

    const int HW  = H * Wd;
    const int co0 = coTile * NTILE;
    const int bz  = blockIdx.z;
    const int p0  = blockIdx.x * 128;
    const int nchunks = K >> 6;

    constexpr int WN  = NTILE / 2;
    constexpr int N8T = WN / 8;
    const int wid  = tid >> 5, lane = tid & 31;
    const int m_base = (wid & 3) * 32;
    const int n_base = (wid >> 2) * WN;

    const uint32_t aHI = dyn, aLO = dyn + 16384;
    const uint32_t bHI = dyn + 32768, bLO = dyn + 49152;

    float acc[2][N8T][4];
#pragma unroll
    for (int mt = 0; mt < 2; ++mt)
#pragma unroll
        for (int nt = 0; nt < N8T; ++nt)
#pragma unroll
            for (int r = 0; r < 4; ++r) acc[mt][nt][r] = 0.f;

    const int g = lane >> 3, lr = lane & 7;

    for (int chunk = 0; chunk < nchunks; ++chunk) {
        const int k0 = chunk << 6;
        int t   = k0 / Cin;
        int ci0 = k0 - t * Cin;
        int dy = 0, dx = 0;
        if (taps == 9) { dy = t / 3 - 1; dx = t - (t / 3) * 3 - 1; }

        // ---- A staging: [k=64][px=128] bf16, 256B rows, SWZA ----
        if (INP) {
            const unsigned* in = (const unsigned*)inv;
#pragma unroll
            for (int j = 0; j < 8; ++j) {
                int idx = tid + j * 256;
                int k = idx >> 5, q = idx & 31;
                int pq = p0 + q * 4;
                uint32_t v0, v1, v2, v3;
                const long long base = ((long long)bz * Cin + ci0 + k) * H;
                if (dx == 0) {
                    int py = pq / Wd;
                    int x0 = pq - py * Wd;
                    int yy = py + dy;
                    if (yy >= 0 && yy < H) {
                        const uint4 u = *(const uint4*)(in + (base + yy) * Wd + x0);
                        v0 = u.x; v1 = u.y; v2 = u.z; v3 = u.w;
                    } else v0 = v1 = v2 = v3 = 0u;
                } else {
                    uint32_t vv[4];
#pragma unroll
                    for (int e = 0; e < 4; ++e) {
                        int p = pq + e;
                        int py = p / Wd, px = p - py * Wd;
                        int yy = py + dy, xx = px + dx;
                        vv[e] = (yy >= 0 && yy < H && xx >= 0 && xx < Wd)
                                    ? __ldg(in + (base + yy) * Wd + xx) : 0u;
                    }
                    v0 = vv[0]; v1 = vv[1]; v2 = vv[2]; v3 = vv[3];
                }
                uint32_t h01 = __byte_perm(v0, v1, 0x5410);
                uint32_t h23 = __byte_perm(v2, v3, 0x5410);
                uint32_t l01 = __byte_perm(v0, v1, 0x7632);
                uint32_t l23 = __byte_perm(v2, v3, 0x7632);
                uint32_t off = SWZA((uint32_t)k * 256u + (uint32_t)q * 8u);
                *(uint2*)(db + off)         = make_uint2(h01, h23);
                *(uint2*)(db + 16384 + off) = make_uint2(l01, l23);
            }
        } else {
            const float* in = (const float*)inv;
#pragma unroll
            for (int j = 0; j < 8; ++j) {
                int idx = tid + j * 256;
                int k = idx >> 5, q = idx & 31;
                int pq = p0 + q * 4;
                float v[4];
                const long long base = ((long long)bz * Cin + ci0 + k) * H;
                if (dx == 0) {
                    int py = pq / Wd;
                    int x0 = pq - py * Wd;
                    int yy = py + dy;
                    if (yy >= 0 && yy < H) {
                        const float4 f4 = *(const float4*)(in + (base + yy) * Wd + x0);
                        v[0] = f4.x; v[1] = f4.y; v[2] = f4.z; v[3] = f4.w;
                    } else v[0] = v[1] = v[2] = v[3] = 0.f;
                } else {
#pragma unroll
                    for (int e = 0; e < 4; ++e) {
                        int p = pq + e;
                        int py = p / Wd, px = p - py * Wd;
                        int yy = py + dy, xx = px + dx;
                        v[e] = (yy >= 0 && yy < H && xx >= 0 && xx < Wd)
                                   ? __ldg(in + (base + yy) * Wd + xx) : 0.f;
                    }
                }
                uint32_t h01, h23, l01, l23;
                CVT2BF(h01, v[1], v[0]);
                CVT2BF(h23, v[3], v[2]);
                float r0 = v[0] - __uint_as_float((h01 & 0xFFFFu) << 16);
                float r1 = v[1] - __uint_as_float(h01 & 0xFFFF0000u);
                float r2 = v[2] - __uint_as_float((h23 & 0xFFFFu) << 16);
                float r3 = v[3] - __uint_as_float(h23 & 0xFFFF0000u);
                CVT2BF(l01, r1, r0);
                CVT2BF(l23, r3, r2);
                uint32_t off = SWZA((uint32_t)k * 256u + (uint32_t)q * 8u);
                *(uint2*)(db + off)         = make_uint2(h01, h23);
                *(uint2*)(db + 16384 + off) = make_uint2(l01, l23);
            }
        }
        // ---- B staging: [co=NTILE][k=64] bf16, 128B rows, SW128 ----
        {
            const char* sH = (const char*)(whi + (long long)co0 * K + k0);
            const char* sL = (const char*)(wlo + (long long)co0 * K + k0);
            const long long rowb = (long long)K * 2;
#pragma unroll
            for (int j = 0; j < (NTILE * 8 + 255) / 256; ++j) {
                int idx = tid + j * 256;
                if (idx < NTILE * 8) {
                    int r = idx >> 3, c = idx & 7;
                    uint4 hv = *(const uint4*)(sH + r * rowb + c * 16);
                    uint4 lv = *(const uint4*)(sL + r * rowb + c * 16);
                    uint32_t off = SWZ((uint32_t)r * 128u + (uint32_t)c * 16u);
                    *(uint4*)(db + 32768 + off) = hv;
                    *(uint4*)(db + 49152 + off) = lv;
                }
            }
        }
        __syncthreads();

        // ---- MMA: 4 k16 steps, 3 terms ----
#pragma unroll
        for (int s = 0; s < 4; ++s) {
            uint32_t bh[N8T][2];
            if constexpr (N8T == 1) {
                uint32_t ad = bHI + SWZ((uint32_t)((n_base + lr) * 128 + s * 32 + (g & 1) * 16));
                LDSM_X2(bh[0][0], bh[0][1], ad);
            } else {
#pragma unroll
                for (int np = 0; np < N8T / 2; ++np) {
                    int nrow = n_base + np * 16 + (g >> 1) * 8 + lr;
                    uint32_t ad = bHI + SWZ((uint32_t)(nrow * 128 + s * 32 + (g & 1) * 16));
                    LDSM_X4(bh[np*2][0], bh[np*2][1], bh[np*2+1][0], bh[np*2+1][1], ad);
                }
            }
            uint32_t ah[2][4];
#pragma unroll
            for (int mt = 0; mt < 2; ++mt) {
                int krow = s * 16 + (g >> 1) * 8 + lr;
                int colb = (m_base + mt * 16 + (g & 1) * 8) * 2;
                uint32_t ad = aHI + SWZA((uint32_t)(krow * 256 + colb));
                LDSM_X4T(ah[mt][0], ah[mt][1], ah[mt][2], ah[mt][3], ad);
            }
#pragma unroll
            for (int mt = 0; mt < 2; ++mt)
#pragma unroll
                for (int nt = 0; nt < N8T; ++nt)
                    MMA16816(acc[mt][nt], ah[mt], bh[nt]);

            uint32_t al[2][4];
#pragma unroll
            for (int mt = 0; mt < 2; ++mt) {
                int krow = s * 16 + (g >> 1) * 8 + lr;
                int colb = (m_base + mt * 16 + (g & 1) * 8) * 2;
                uint32_t ad = aLO + SWZA((uint32_t)(krow * 256 + colb));
                LDSM_X4T(al[mt][0], al[mt][1], al[mt][2], al[mt][3], ad);
            }
#pragma unroll
            for (int mt = 0; mt < 2; ++mt)
#pragma unroll
                for (int nt = 0; nt < N8T; ++nt)
                    MMA16816(acc[mt][nt], al[mt], bh[nt]);

            uint32_t bl[N8T][2];
            if constexpr (N8T == 1) {
                uint32_t ad = bLO + SWZ((uint32_t)((n_base + lr) * 128 + s * 32 + (g & 1) * 16));
                LDSM_X2(bl[0][0], bl[0][1], ad);
            } else {
#pragma unroll
                for (int np = 0; np < N8T / 2; ++np) {
                    int nrow = n_base + np * 16 + (g >> 1) * 8 + lr;
                    uint32_t ad = bLO + SWZ((uint32_t)(nrow * 128 + s * 32 + (g & 1) * 16));
                    LDSM_X4(bl[np*2][0], bl[np*2][1], bl[np*2+1][0], bl[np*2+1][1], ad);
                }
            }
#pragma unroll
            for (int mt = 0; mt < 2; ++mt)
#pragma unroll
                for (int nt = 0; nt < N8T; ++nt)
                    MMA16816(acc[mt][nt], ah[mt], bl[nt]);
        }
        __syncthreads();
    }

    // ---- epilogue ----
    const long long obase = (long long)bz * ob;
#pragma unroll
    for (int mt = 0; mt < 2; ++mt)
#pragma unroll
        for (int nt = 0; nt < N8T; ++nt)
#pragma unroll
            for (int rg = 0; rg < 4; ++rg) {
                int m  = m_base + mt * 16 + (lane >> 2) + ((rg >= 2) ? 8 : 0);
                int co = co0 + n_base + nt * 8 + (lane & 3) * 2 + (rg & 1);
                if (co < CoutActual) {
                    float v = acc[mt][nt][rg] + bias[co];
                    if (RELU) v = fmaxf(v, 0.f);
                    long long off = obase + (long long)co * oc + (long long)(p0 + m) * op;
                    if (OUTP) ((unsigned*)outv)[off] = packf(v);
                    else      ((float*)outv)[off]    = v;
                }
            }
}

// ---------------- nearest 2x upsample + add (packed domain) ------------------
__global__ void up2add_kernel(unsigned* __restrict__ big,
                              const unsigned* __restrict__ small, int Hs, int Ws)
{
    const int H = Hs * 2, W = Ws * 2;
    const long long total = 8LL * 256 * H * W;
    long long idx = (long long)blockIdx.x * blockDim.x + threadIdx.x;
    if (idx >= total) return;
    int x = (int)(idx % W);
    int y = (int)((idx / W) % H);
    long long bc = idx / ((long long)W * H);
    float v = unpackf(big[idx]) + unpackf(small[(bc * Hs + (y >> 1)) * Ws + (x >> 1)]);
    big[idx] = packf(v);
}

// ---------------- anchors ----------------------------------------------------
__global__ void anchors_kernel(float* __restrict__ out)
{
    int i = blockIdx.x * blockDim.x + threadIdx.x;
    if (i >= 16128) return;
    int lvl, rem;
    if (i < 12288)      { lvl = 0; rem = i; }
    else if (i < 15360) { lvl = 1; rem = i - 12288; }
    else                { lvl = 2; rem = i - 15360; }
    const int w        = 64 >> lvl;
    const float stride = 8.0f * (float)(1 << lvl);
    const float bs     = 32.0f * (float)(1 << lvl);
    const int a = rem % 3;
    const int s = rem / 3;
    const int x = s % w;
    const int y = s / w;
    const float sq[3] = {0.70710678118654752f, 1.0f, 1.41421356237309505f};
    const float hw = bs * sq[a] * 0.5f;
    const float hh = bs / sq[a] * 0.5f;
    const float cx = (float)x * stride;
    const float cy = (float)y * stride;
    float* o = out + (long long)i * 4;
    o[0] = cx - hw; o[1] = cy - hh; o[2] = cx + hw; o[3] = cy + hh;
}

// ---------------- host dispatch ----------------------------------------------
static const size_t GEMM_SMEM = 66560;

extern "C" void kernel_launch(void* const* d_in, const int* in_sizes, int n_in,
                              void* d_out, int out_size)
{
    const float* feat3 = (const float*)d_in[0];
    const float* feat4 = (const float*)d_in[1];
    const float* feat5 = (const float*)d_in[2];
    const float* lw0 = (const float*)d_in[3];  const float* lb0 = (const float*)d_in[4];
    const float* lw1 = (const float*)d_in[5];  const float* lb1 = (const float*)d_in[6];
    const float* lw2 = (const float*)d_in[7];  const float* lb2 = (const float*)d_in[8];
    const float* fw0 = (const float*)d_in[9];  const float* fb0 = (const float*)d_in[10];
    const float* fw1 = (const float*)d_in[11]; const float* fb1 = (const float*)d_in[12];
    const float* fw2 = (const float*)d_in[13]; const float* fb2 = (const float*)d_in[14];
    const float* cw0 = (const float*)d_in[15]; const float* cb0 = (const float*)d_in[16];
    const float* cw1 = (const float*)d_in[17]; const float* cb1 = (const float*)d_in[18];
    const float* cw2 = (const float*)d_in[19]; const float* cb2 = (const float*)d_in[20];
    const float* rw0 = (const float*)d_in[21]; const float* rb0 = (const float*)d_in[22];
    const float* rw1 = (const float*)d_in[23]; const float* rb1 = (const float*)d_in[24];
    const float* rw2 = (const float*)d_in[25]; const float* rb2 = (const float*)d_in[26];
    float* out = (float*)d_out;

    cudaFuncSetAttribute(gemm_conv<128, false, false, true>,  cudaFuncAttributeMaxDynamicSharedMemorySize, (int)GEMM_SMEM);
    cudaFuncSetAttribute(gemm_conv<128, false, true,  true>,  cudaFuncAttributeMaxDynamicSharedMemorySize, (int)GEMM_SMEM);
    cudaFuncSetAttribute(gemm_conv<128, true,  true,  true>,  cudaFuncAttributeMaxDynamicSharedMemorySize, (int)GEMM_SMEM);
    cudaFuncSetAttribute(gemm_conv<128, false, true,  false>, cudaFuncAttributeMaxDynamicSharedMemorySize, (int)GEMM_SMEM);
    cudaFuncSetAttribute(gemm_conv<16,  false, true,  false>, cudaFuncAttributeMaxDynamicSharedMemorySize, (int)GEMM_SMEM);

    unsigned *l0, *l1, *l2, *f, *t1c, *t1r, *t2c, *t2r;
    __nv_bfloat16 *whi, *wlo;
    cudaGetSymbolAddress((void**)&l0,  g_l0);
    cudaGetSymbolAddress((void**)&l1,  g_l1);
    cudaGetSymbolAddress((void**)&l2,  g_l2);
    cudaGetSymbolAddress((void**)&f,   g_f);
    cudaGetSymbolAddress((void**)&t1c, g_t1c);
    cudaGetSymbolAddress((void**)&t1r, g_t1r);
    cudaGetSymbolAddress((void**)&t2c, g_t2c);
    cudaGetSymbolAddress((void**)&t2r, g_t2r);
    cudaGetSymbolAddress((void**)&whi, g_whi);
    cudaGetSymbolAddress((void**)&wlo, g_wlo);

    // ---- merged weight pre-transform ----
    {
        WtTab T;
        const WtEnt ents[12] = {
            { lw0, WOFF_L0,  WOFF_L1  - WOFF_L0,  256, 512,  1 },
            { lw1, WOFF_L1,  WOFF_L2  - WOFF_L1,  256, 1024, 1 },
            { lw2, WOFF_L2,  WOFF_FW0 - WOFF_L2,  256, 2048, 1 },
            { fw0, WOFF_FW0, WOFF_FW1 - WOFF_FW0, 256, 256,  9 },
            { fw1, WOFF_FW1, WOFF_FW2 - WOFF_FW1, 256, 256,  9 },
            { fw2, WOFF_FW2, WOFF_CW0 - WOFF_FW2, 256, 256,  9 },
            { cw0, WOFF_CW0, WOFF_CW1 - WOFF_CW0, 256, 256,  9 },
            { cw1, WOFF_CW1, WOFF_CW2 - WOFF_CW1, 256, 256,  9 },
            { cw2, WOFF_CW2, WOFF_RW0 - WOFF_CW2, 240, 256,  9 },
            { rw0, WOFF_RW0, WOFF_RW1 - WOFF_RW0, 256, 256,  9 },
            { rw1, WOFF_RW1, WOFF_RW2 - WOFF_RW1, 256, 256,  9 },
            { rw2, WOFF_RW2, WARENA   - WOFF_RW2, 12,  256,  9 },
        };
        for (int i = 0; i < 12; ++i) T.e[i] = ents[i];
        wt_all<<<(unsigned)((WARENA + 255) / 256), 256>>>(T, whi, wlo);
    }

    // ---- FPN laterals (fp32 in, packed out) ----
    {
        GArgs a0 = { feat3, whi + WOFF_L0, wlo + WOFF_L0, lb0, l0 };
        gemm_conv<128, false, false, true><<<dim3(32, 2, 8), 256, GEMM_SMEM>>>(
            a0, a0, 2, 512, 256, 512, 1, 64, 64, 256LL * 4096, 4096, 1);
        GArgs a1 = { feat4, whi + WOFF_L1, wlo + WOFF_L1, lb1, l1 };
        gemm_conv<128, false, false, true><<<dim3(8, 2, 8), 256, GEMM_SMEM>>>(
            a1, a1, 2, 1024, 256, 1024, 1, 32, 32, 256LL * 1024, 1024, 1);
        GArgs a2 = { feat5, whi + WOFF_L2, wlo + WOFF_L2, lb2, l2 };
        gemm_conv<128, false, false, true><<<dim3(2, 2, 8), 256, GEMM_SMEM>>>(
            a2, a2, 2, 2048, 256, 2048, 1, 16, 16, 256LL * 256, 256, 1);
    }

    // ---- top-down merge (packed) ----
    {
        long long n1 = 8LL * 256 * 32 * 32;
        up2add_kernel<<<(unsigned)((n1 + 255) / 256), 256>>>(l1, l2, 16, 16);
        long long n0 = 8LL * 256 * 64 * 64;
        up2add_kernel<<<(unsigned)((n0 + 255) / 256), 256>>>(l0, l1, 32, 32);
    }

    struct Lvl { const unsigned* lat; long long fwoff; const float* fb; int H, W; long long poff; };
    const Lvl L[3] = {
        { l0, WOFF_FW0, fb0, 64, 64, 0    },
        { l1, WOFF_FW1, fb1, 32, 32, 4096 },
        { l2, WOFF_FW2, fb2, 16, 16, 5120 },
    };

    for (int i = 0; i < 3; ++i) {
        const int H = L[i].H, W = L[i].W;
        const long long hw = (long long)H * W;
        const int gx = (int)(hw / 128);

        // FPN 3x3 output conv (packed in/out)
        {
            GArgs a = { L[i].lat, whi + L[i].fwoff, wlo + L[i].fwoff, L[i].fb, f };
            gemm_conv<128, false, true, true><<<dim3(gx, 2, 8), 256, GEMM_SMEM>>>(
                a, a, 2, 256, 256, 2304, 9, H, W, 256 * hw, hw, 1);
        }
        // tower conv1 (fused cls+reg)
        {
            GArgs ac = { f, whi + WOFF_CW0, wlo + WOFF_CW0, cb0, t1c };
            GArgs ar = { f, whi + WOFF_RW0, wlo + WOFF_RW0, rb0, t1r };
            gemm_conv<128, true, true, true><<<dim3(gx, 4, 8), 256, GEMM_SMEM>>>(
                ac, ar, 2, 256, 256, 2304, 9, H, W, 256 * hw, hw, 1);
        }
        // tower conv2 (fused cls+reg)
        {
            GArgs ac = { t1c, whi + WOFF_CW1, wlo + WOFF_CW1, cb1, t2c };
            GArgs ar = { t1r, whi + WOFF_RW1, wlo + WOFF_RW1, rb1, t2r };
            gemm_conv<128, true, true, true><<<dim3(gx, 4, 8), 256, GEMM_SMEM>>>(
                ac, ar, 2, 256, 256, 2304, 9, H, W, 256 * hw, hw, 1);
        }
        // cls final (packed in, fp32 strided out)
        {
            GArgs a = { t2c, whi + WOFF_CW2, wlo + WOFF_CW2, cb2, out + L[i].poff * 252 };
            gemm_conv<128, false, true, false><<<dim3(gx, 2, 8), 256, GEMM_SMEM>>>(
                a, a, 2, 256, 240, 2304, 9, H, W, 5376LL * 252, 1, 252);
        }
        // reg final (packed in, fp32 strided out)
        {
            GArgs a = { t2r, whi + WOFF_RW2, wlo + WOFF_RW2, rb2, out + L[i].poff * 252 + 240 };
            gemm_conv<16, false, true, false><<<dim3(gx, 1, 8), 256, GEMM_SMEM>>>(
                a, a, 1, 256, 12, 2304, 9, H, W, 5376LL * 252, 1, 252);
        }
    }

    anchors_kernel<<<(16128 + 255) / 256, 256>>>(out + 10838016LL);
}

// round 5
// speedup vs baseline: 1.6002x; 1.6002x over previous
#include <cuda_runtime.h>
#include <cuda_bf16.h>
#include <cstdint>

// ---------------- packed bf16 hi/lo intermediates (u32 = lo16<<16 | hi16) ----
// per-level segments inside f/t buffers: lvl0 [0, 8*256*4096), lvl1, lvl2
#define SEG1 8388608LL
#define SEG2 10485760LL
__device__ __align__(16) unsigned g_l0 [8 * 256 * 4096];
__device__ __align__(16) unsigned g_l1 [8 * 256 * 1024];
__device__ __align__(16) unsigned g_l2 [8 * 256 * 256];
__device__ __align__(16) unsigned g_f  [8 * 256 * 5376];
__device__ __align__(16) unsigned g_t1c[8 * 256 * 5376];
__device__ __align__(16) unsigned g_t1r[8 * 256 * 5376];
__device__ __align__(16) unsigned g_t2c[8 * 256 * 5376];
__device__ __align__(16) unsigned g_t2r[8 * 256 * 5376];
// split-K partial scratch (fp32)
__device__ __align__(16) float g_sk1[4 * 8 * 256 * 1024];
__device__ __align__(16) float g_sk2[8 * 8 * 256 * 256];

// ---------------- bf16 hi/lo weight arena (t-major K layout) -----------------
#define WOFF_L0  0LL
#define WOFF_L1  131072LL
#define WOFF_L2  393216LL
#define WOFF_FW0 917504LL
#define WOFF_FW1 1507328LL
#define WOFF_FW2 2097152LL
#define WOFF_CW0 2686976LL
#define WOFF_CW1 3276800LL
#define WOFF_CW2 3866624LL
#define WOFF_RW0 4456448LL
#define WOFF_RW1 5046272LL
#define WOFF_RW2 5636096LL
#define WARENA   5672960LL
__device__ __nv_bfloat16 g_whi[WARENA];
__device__ __nv_bfloat16 g_wlo[WARENA];

// ---------------- helpers ----------------------------------------------------
#define SWZ(off)  ((off) ^ (((off) >> 3) & 0x70))   // 128B-row swizzle
#define SWZA(off) ((off) ^ (((off) >> 4) & 0x70))   // 256B-row swizzle

static __device__ __forceinline__ uint32_t smem_u32(const void* p) {
    uint32_t a;
    asm("{ .reg .u64 t; cvta.to.shared.u64 t, %1; cvt.u32.u64 %0, t; }"
        : "=r"(a) : "l"(p));
    return a;
}
static __device__ __forceinline__ uint32_t packf(float v) {
    uint32_t vb = __float_as_uint(v);
    uint32_t hb = (vb + 0x7FFFu + ((vb >> 16) & 1u)) & 0xFFFF0000u;
    float r = v - __uint_as_float(hb);
    uint32_t rb = __float_as_uint(r);
    uint32_t lb = (rb + 0x7FFFu + ((rb >> 16) & 1u)) & 0xFFFF0000u;
    return (hb >> 16) | lb;
}
static __device__ __forceinline__ float unpackf(uint32_t p) {
    return __uint_as_float(p << 16) + __uint_as_float(p & 0xFFFF0000u);
}

#define LDSM_X4(r0, r1, r2, r3, ad) \
    asm volatile("ldmatrix.sync.aligned.m8n8.x4.shared.b16 {%0,%1,%2,%3}, [%4];" \
                 : "=r"(r0), "=r"(r1), "=r"(r2), "=r"(r3) : "r"(ad))
#define LDSM_X4T(r0, r1, r2, r3, ad) \
    asm volatile("ldmatrix.sync.aligned.m8n8.x4.trans.shared.b16 {%0,%1,%2,%3}, [%4];" \
                 : "=r"(r0), "=r"(r1), "=r"(r2), "=r"(r3) : "r"(ad))
#define LDSM_X2(r0, r1, ad) \
    asm volatile("ldmatrix.sync.aligned.m8n8.x2.shared.b16 {%0,%1}, [%2];" \
                 : "=r"(r0), "=r"(r1) : "r"(ad))
#define MMA16816(d, a, b) \
    asm volatile("mma.sync.aligned.m16n8k16.row.col.f32.bf16.bf16.f32 " \
                 "{%0,%1,%2,%3},{%4,%5,%6,%7},{%8,%9},{%0,%1,%2,%3};" \
                 : "+f"((d)[0]), "+f"((d)[1]), "+f"((d)[2]), "+f"((d)[3]) \
                 : "r"((a)[0]), "r"((a)[1]), "r"((a)[2]), "r"((a)[3]), \
                   "r"((b)[0]), "r"((b)[1]))
#define CVT2BF(dst, hi, lo) \
    asm("cvt.rn.bf16x2.f32 %0, %1, %2;" : "=r"(dst) : "f"(hi), "f"(lo))

// ---------------- shared MMA inner section (one 64-k chunk) ------------------
template <int N8T>
static __device__ __forceinline__ void mma_chunk(
    uint32_t aHI, uint32_t aLO, uint32_t bHI, uint32_t bLO,
    float (&acc)[2][N8T][4], int m_base, int n_base, int g, int lr)
{
#pragma unroll
    for (int s = 0; s < 4; ++s) {
        uint32_t bh[N8T][2];
        if constexpr (N8T == 1) {
            uint32_t ad = bHI + SWZ((uint32_t)((n_base + lr) * 128 + s * 32 + (g & 1) * 16));
            LDSM_X2(bh[0][0], bh[0][1], ad);
        } else {
#pragma unroll
            for (int np = 0; np < N8T / 2; ++np) {
                int nrow = n_base + np * 16 + (g >> 1) * 8 + lr;
                uint32_t ad = bHI + SWZ((uint32_t)(nrow * 128 + s * 32 + (g & 1) * 16));
                LDSM_X4(bh[np*2][0], bh[np*2][1], bh[np*2+1][0], bh[np*2+1][1], ad);
            }
        }
        uint32_t ah[2][4];
#pragma unroll
        for (int mt = 0; mt < 2; ++mt) {
            int krow = s * 16 + (g >> 1) * 8 + lr;
            int colb = (m_base + mt * 16 + (g & 1) * 8) * 2;
            uint32_t ad = aHI + SWZA((uint32_t)(krow * 256 + colb));
            LDSM_X4T(ah[mt][0], ah[mt][1], ah[mt][2], ah[mt][3], ad);
        }
#pragma unroll
        for (int mt = 0; mt < 2; ++mt)
#pragma unroll
            for (int nt = 0; nt < N8T; ++nt)
                MMA16816(acc[mt][nt], ah[mt], bh[nt]);

        uint32_t al[2][4];
#pragma unroll
        for (int mt = 0; mt < 2; ++mt) {
            int krow = s * 16 + (g >> 1) * 8 + lr;
            int colb = (m_base + mt * 16 + (g & 1) * 8) * 2;
            uint32_t ad = aLO + SWZA((uint32_t)(krow * 256 + colb));
            LDSM_X4T(al[mt][0], al[mt][1], al[mt][2], al[mt][3], ad);
        }
#pragma unroll
        for (int mt = 0; mt < 2; ++mt)
#pragma unroll
            for (int nt = 0; nt < N8T; ++nt)
                MMA16816(acc[mt][nt], al[mt], bh[nt]);

        uint32_t bl[N8T][2];
        if constexpr (N8T == 1) {
            uint32_t ad = bLO + SWZ((uint32_t)((n_base + lr) * 128 + s * 32 + (g & 1) * 16));
            LDSM_X2(bl[0][0], bl[0][1], ad);
        } else {
#pragma unroll
            for (int np = 0; np < N8T / 2; ++np) {
                int nrow = n_base + np * 16 + (g >> 1) * 8 + lr;
                uint32_t ad = bLO + SWZ((uint32_t)(nrow * 128 + s * 32 + (g & 1) * 16));
                LDSM_X4(bl[np*2][0], bl[np*2][1], bl[np*2+1][0], bl[np*2+1][1], ad);
            }
        }
#pragma unroll
        for (int mt = 0; mt < 2; ++mt)
#pragma unroll
            for (int nt = 0; nt < N8T; ++nt)
                MMA16816(acc[mt][nt], ah[mt], bl[nt]);
    }
}

// ---------------- merged weight pre-transform --------------------------------
struct WtEnt { const float* src; long long start; int coutA; int cin; int taps; };
struct WtTab { WtEnt e[12]; };

__global__ void wt_all(WtTab T, __nv_bfloat16* __restrict__ hi,
                       __nv_bfloat16* __restrict__ lo)
{
    long long idx = (long long)blockIdx.x * 256 + threadIdx.x;
    if (idx >= WARENA) return;
    int i = 0;
#pragma unroll
    for (int j = 1; j < 12; ++j) if (idx >= T.e[j].start) i = j;
    const WtEnt E = T.e[i];
    long long local = idx - E.start;
    const int Kk = E.cin * E.taps;
    long long co = local / Kk;
    int r  = (int)(local - co * Kk);
    int t  = r / E.cin;
    int ci = r - t * E.cin;
    float v = 0.f;
    if (co < E.coutA) v = E.src[co * Kk + (long long)ci * E.taps + t];
    __nv_bfloat16 h = __float2bfloat16(v);
    float rr = v - __bfloat162float(h);
    hi[idx] = h;
    lo[idx] = __float2bfloat16(rr);
}

// ---------------- lateral 1x1 GEMM (fp32 in), optional split-K ---------------
template <bool SPLIT>
__global__ void __launch_bounds__(256, 2)
lat_gemm(const float* __restrict__ in, const __nv_bfloat16* __restrict__ wh,
         const __nv_bfloat16* __restrict__ wl, const float* __restrict__ bias,
         void* outv, int Cin, int logW, int chunksPer, long long sliceStride)
{
    extern __shared__ char dsm[];
    const int tid = threadIdx.x;
    uint32_t u0  = smem_u32(dsm);
    uint32_t pad = (1024u - (u0 & 1023u)) & 1023u;
    char*    db  = dsm + pad;
    uint32_t dyn = u0 + pad;

    const int yb = blockIdx.y;
    const int coTile = yb & 1, slice = yb >> 1;
    const int HW = 1 << (2 * logW);
    const int co0 = coTile * 128;
    const int bz  = blockIdx.z;
    const int p0  = blockIdx.x * 128;
    const int c0  = SPLIT ? slice * chunksPer : 0;
    const int nch = SPLIT ? chunksPer : (Cin >> 6);
    const int K   = Cin;

    const int wid = tid >> 5, lane = tid & 31;
    const int m_base = (wid & 3) * 32;
    const int n_base = (wid >> 2) * 64;
    const int g = lane >> 3, lr = lane & 7;

    const uint32_t aHI = dyn, aLO = dyn + 16384;
    const uint32_t bHI = dyn + 32768, bLO = dyn + 49152;

    float acc[2][8][4];
#pragma unroll
    for (int mt = 0; mt < 2; ++mt)
#pragma unroll
        for (int nt = 0; nt < 8; ++nt)
#pragma unroll
            for (int r = 0; r < 4; ++r) acc[mt][nt][r] = 0.f;

    for (int cc = 0; cc < nch; ++cc) {
        const int k0 = (c0 + cc) << 6;
        // A staging: fp32 -> hi/lo bf16, [k=64][px=128], contiguous rows
#pragma unroll
        for (int j = 0; j < 8; ++j) {
            int idx = tid + j * 256;
            int k = idx >> 5, q = idx & 31;
            const float4 f4 = *(const float4*)(in +
                ((long long)(bz * Cin + k0 + k)) * HW + p0 + q * 4);
            float v0 = f4.x, v1 = f4.y, v2 = f4.z, v3 = f4.w;
            uint32_t h01, h23, l01, l23;
            CVT2BF(h01, v1, v0);
            CVT2BF(h23, v3, v2);
            float r0 = v0 - __uint_as_float((h01 & 0xFFFFu) << 16);
            float r1 = v1 - __uint_as_float(h01 & 0xFFFF0000u);
            float r2 = v2 - __uint_as_float((h23 & 0xFFFFu) << 16);
            float r3 = v3 - __uint_as_float(h23 & 0xFFFF0000u);
            CVT2BF(l01, r1, r0);
            CVT2BF(l23, r3, r2);
            uint32_t off = SWZA((uint32_t)k * 256u + (uint32_t)q * 8u);
            *(uint2*)(db + off)         = make_uint2(h01, h23);
            *(uint2*)(db + 16384 + off) = make_uint2(l01, l23);
        }
        // B staging
        {
            const char* sH = (const char*)(wh + (long long)co0 * K + k0);
            const char* sL = (const char*)(wl + (long long)co0 * K + k0);
            const long long rowb = (long long)K * 2;
#pragma unroll
            for (int j = 0; j < 4; ++j) {
                int idx = tid + j * 256;
                int r = idx >> 3, c = idx & 7;
                uint4 hv = *(const uint4*)(sH + r * rowb + c * 16);
                uint4 lv = *(const uint4*)(sL + r * rowb + c * 16);
                uint32_t off = SWZ((uint32_t)r * 128u + (uint32_t)c * 16u);
                *(uint4*)(db + 32768 + off) = hv;
                *(uint4*)(db + 49152 + off) = lv;
            }
        }
        __syncthreads();
        mma_chunk<8>(aHI, aLO, bHI, bLO, acc, m_base, n_base, g, lr);
        __syncthreads();
    }

    // epilogue
#pragma unroll
    for (int mt = 0; mt < 2; ++mt)
#pragma unroll
        for (int nt = 0; nt < 8; ++nt)
#pragma unroll
            for (int rg = 0; rg < 4; ++rg) {
                int m  = m_base + mt * 16 + (lane >> 2) + ((rg >= 2) ? 8 : 0);
                int co = co0 + n_base + nt * 8 + (lane & 3) * 2 + (rg & 1);
                long long off = ((long long)(bz * 256 + co)) * HW + p0 + m;
                if (SPLIT) {
                    ((float*)outv)[slice * sliceStride + off] = acc[mt][nt][rg];
                } else {
                    ((unsigned*)outv)[off] = packf(acc[mt][nt][rg] + bias[co]);
                }
            }
}

// ---------------- split-K reduce (+bias, pack) --------------------------------
__global__ void red_kernel(const float* __restrict__ src, unsigned* __restrict__ dst,
                           const float* __restrict__ bias, int slices,
                           long long sliceStride, int logHW, long long n)
{
    long long idx = (long long)blockIdx.x * 256 + threadIdx.x;
    if (idx >= n) return;
    float v = bias[(int)((idx >> logHW) & 255)];
    for (int s = 0; s < slices; ++s) v += src[s * sliceStride + idx];
    dst[idx] = packf(v);
}

// ---------------- multi-level 3x3 tower GEMM (packed in) ---------------------
struct TArgs {
    const unsigned* in[3];
    void* out[3];
    const __nv_bfloat16* wh[3];
    const __nv_bfloat16* wl[3];
    const float* bias[3];
    long long ob[3];
    long long oc[3];
    long long op;
};

template <int NTILE, bool RELU, bool OUTP>
__global__ void __launch_bounds__(256, 2)
tower_gemm(TArgs T, int CoutActual)
{
    extern __shared__ char dsm[];
    const int tid = threadIdx.x;
    uint32_t u0  = smem_u32(dsm);
    uint32_t pad = (1024u - (u0 & 1023u)) & 1023u;
    char*    db  = dsm + pad;
    uint32_t dyn = u0 + pad;

    // level lookup from blockIdx.x (42 = 32 + 8 + 2)
    const int xb  = blockIdx.x;
    const int lvl = (xb >= 40) ? 2 : ((xb >= 32) ? 1 : 0);
    const int xl  = xb - ((lvl == 2) ? 40 : ((lvl == 1) ? 32 : 0));
    const int logW = 6 - lvl;
    const int W    = 1 << logW;
    const int HW   = 1 << (2 * logW);

    const unsigned* __restrict__ in = T.in[lvl];
    const __nv_bfloat16* wh = T.wh[lvl];
    const __nv_bfloat16* wl = T.wl[lvl];
    const float* bias = T.bias[lvl];

    const int coTile = blockIdx.y;
    const int co0 = coTile * NTILE;
    const int bz  = blockIdx.z;
    const int p0  = xl * 128;
    constexpr int K = 2304;

    constexpr int WN  = NTILE / 2;
    constexpr int N8T = WN / 8;
    const int wid = tid >> 5, lane = tid & 31;
    const int m_base = (wid & 3) * 32;
    const int n_base = (wid >> 2) * WN;
    const int g = lane >> 3, lr = lane & 7;

    const uint32_t aHI = dyn, aLO = dyn + 16384;
    const uint32_t bHI = dyn + 32768, bLO = dyn + 49152;

    float acc[2][N8T][4];
#pragma unroll
    for (int mt = 0; mt < 2; ++mt)
#pragma unroll
        for (int nt = 0; nt < N8T; ++nt)
#pragma unroll
            for (int r = 0; r < 4; ++r) acc[mt][nt][r] = 0.f;

    for (int chunk = 0; chunk < 36; ++chunk) {
        const int k0 = chunk << 6;
        const int t  = k0 >> 8;
        const int ci0 = k0 & 255;
        const int dy = t / 3 - 1;
        const int dx = t - (t / 3) * 3 - 1;

        // A staging: packed u32 -> hi/lo planes, [k=64][px=128]
#pragma unroll
        for (int j = 0; j < 8; ++j) {
            int idx = tid + j * 256;
            int k = idx >> 5, q = idx & 31;
            int pq = p0 + q * 4;
            const long long base = ((long long)(bz * 256 + ci0 + k)) << (2 * logW);
            uint32_t v0, v1, v2, v3;
            if (dx == 0) {
                int py = pq >> logW;
                int x0 = pq & (W - 1);
                int yy = py + dy;
                if ((unsigned)yy < (unsigned)W) {
                    const uint4 u = *(const uint4*)(in + base + ((long long)yy << logW) + x0);
                    v0 = u.x; v1 = u.y; v2 = u.z; v3 = u.w;
                } else v0 = v1 = v2 = v3 = 0u;
            } else {
                uint32_t vv[4];
#pragma unroll
                for (int e = 0; e < 4; ++e) {
                    int p = pq + e;
                    int py = p >> logW, px = p & (W - 1);
                    int yy = py + dy, xx = px + dx;
                    vv[e] = ((unsigned)yy < (unsigned)W && (unsigned)xx < (unsigned)W)
                                ? __ldg(in + base + ((long long)yy << logW) + xx) : 0u;
                }
                v0 = vv[0]; v1 = vv[1]; v2 = vv[2]; v3 = vv[3];
            }
            uint32_t h01 = __byte_perm(v0, v1, 0x5410);
            uint32_t h23 = __byte_perm(v2, v3, 0x5410);
            uint32_t l01 = __byte_perm(v0, v1, 0x7632);
            uint32_t l23 = __byte_perm(v2, v3, 0x7632);
            uint32_t off = SWZA((uint32_t)k * 256u + (uint32_t)q * 8u);
            *(uint2*)(db + off)         = make_uint2(h01, h23);
            *(uint2*)(db + 16384 + off) = make_uint2(l01, l23);
        }
        // B staging
        {
            const char* sH = (const char*)(wh + (long long)co0 * K + k0);
            const char* sL = (const char*)(wl + (long long)co0 * K + k0);
            const long long rowb = (long long)K * 2;
#pragma unroll
            for (int j = 0; j < (NTILE * 8 + 255) / 256; ++j) {
                int idx = tid + j * 256;
                if (idx < NTILE * 8) {
                    int r = idx >> 3, c = idx & 7;
                    uint4 hv = *(const uint4*)(sH + r * rowb + c * 16);
                    uint4 lv = *(const uint4*)(sL + r * rowb + c * 16);
                    uint32_t off = SWZ((uint32_t)r * 128u + (uint32_t)c * 16u);
                    *(uint4*)(db + 32768 + off) = hv;
                    *(uint4*)(db + 49152 + off) = lv;
                }
            }
        }
        __syncthreads();
        mma_chunk<N8T>(aHI, aLO, bHI, bLO, acc, m_base, n_base, g, lr);
        __syncthreads();
    }

    // epilogue
    const long long obase = (long long)bz * T.ob[lvl];
    const long long oc = T.oc[lvl];
    const long long op = T.op;
#pragma unroll
    for (int mt = 0; mt < 2; ++mt)
#pragma unroll
        for (int nt = 0; nt < N8T; ++nt)
#pragma unroll
            for (int rg = 0; rg < 4; ++rg) {
                int m  = m_base + mt * 16 + (lane >> 2) + ((rg >= 2) ? 8 : 0);
                int co = co0 + n_base + nt * 8 + (lane & 3) * 2 + (rg & 1);
                if (co < CoutActual) {
                    float v = acc[mt][nt][rg] + bias[co];
                    if (RELU) v = fmaxf(v, 0.f);
                    long long off = obase + (long long)co * oc + (long long)(p0 + m) * op;
                    if (OUTP) ((unsigned*)T.out[lvl])[off] = packf(v);
                    else      ((float*)T.out[lvl])[off]    = v;
                }
            }
}

// ---------------- nearest 2x upsample + add (packed domain) ------------------
__global__ void up2add_kernel(unsigned* __restrict__ big,
                              const unsigned* __restrict__ small, int Hs, int Ws)
{
    const int H = Hs * 2, W = Ws * 2;
    const long long total = 8LL * 256 * H * W;
    long long idx = (long long)blockIdx.x * blockDim.x + threadIdx.x;
    if (idx >= total) return;
    int x = (int)(idx % W);
    int y = (int)((idx / W) % H);
    long long bc = idx / ((long long)W * H);
    float v = unpackf(big[idx]) + unpackf(small[(bc * Hs + (y >> 1)) * Ws + (x >> 1)]);
    big[idx] = packf(v);
}

// ---------------- anchors ----------------------------------------------------
__global__ void anchors_kernel(float* __restrict__ out)
{
    int i = blockIdx.x * blockDim.x + threadIdx.x;
    if (i >= 16128) return;
    int lvl, rem;
    if (i < 12288)      { lvl = 0; rem = i; }
    else if (i < 15360) { lvl = 1; rem = i - 12288; }
    else                { lvl = 2; rem = i - 15360; }
    const int w        = 64 >> lvl;
    const float stride = 8.0f * (float)(1 << lvl);
    const float bs     = 32.0f * (float)(1 << lvl);
    const int a = rem % 3;
    const int s = rem / 3;
    const int x = s % w;
    const int y = s / w;
    const float sq[3] = {0.70710678118654752f, 1.0f, 1.41421356237309505f};
    const float hw = bs * sq[a] * 0.5f;
    const float hh = bs / sq[a] * 0.5f;
    const float cx = (float)x * stride;
    const float cy = (float)y * stride;
    float* o = out + (long long)i * 4;
    o[0] = cx - hw; o[1] = cy - hh; o[2] = cx + hw; o[3] = cy + hh;
}

// ---------------- host dispatch ----------------------------------------------
static const size_t GEMM_SMEM = 66560;

extern "C" void kernel_launch(void* const* d_in, const int* in_sizes, int n_in,
                              void* d_out, int out_size)
{
    const float* feat3 = (const float*)d_in[0];
    const float* feat4 = (const float*)d_in[1];
    const float* feat5 = (const float*)d_in[2];
    const float* lw0 = (const float*)d_in[3];  const float* lb0 = (const float*)d_in[4];
    const float* lw1 = (const float*)d_in[5];  const float* lb1 = (const float*)d_in[6];
    const float* lw2 = (const float*)d_in[7];  const float* lb2 = (const float*)d_in[8];
    const float* fw0 = (const float*)d_in[9];  const float* fb0 = (const float*)d_in[10];
    const float* fw1 = (const float*)d_in[11]; const float* fb1 = (const float*)d_in[12];
    const float* fw2 = (const float*)d_in[13]; const float* fb2 = (const float*)d_in[14];
    const float* cw0 = (const float*)d_in[15]; const float* cb0 = (const float*)d_in[16];
    const float* cw1 = (const float*)d_in[17]; const float* cb1 = (const float*)d_in[18];
    const float* cw2 = (const float*)d_in[19]; const float* cb2 = (const float*)d_in[20];
    const float* rw0 = (const float*)d_in[21]; const float* rb0 = (const float*)d_in[22];
    const float* rw1 = (const float*)d_in[23]; const float* rb1 = (const float*)d_in[24];
    const float* rw2 = (const float*)d_in[25]; const float* rb2 = (const float*)d_in[26];
    float* out = (float*)d_out;

    cudaFuncSetAttribute(lat_gemm<false>, cudaFuncAttributeMaxDynamicSharedMemorySize, (int)GEMM_SMEM);
    cudaFuncSetAttribute(lat_gemm<true>,  cudaFuncAttributeMaxDynamicSharedMemorySize, (int)GEMM_SMEM);
    cudaFuncSetAttribute(tower_gemm<128, false, true>,  cudaFuncAttributeMaxDynamicSharedMemorySize, (int)GEMM_SMEM);
    cudaFuncSetAttribute(tower_gemm<128, true,  true>,  cudaFuncAttributeMaxDynamicSharedMemorySize, (int)GEMM_SMEM);
    cudaFuncSetAttribute(tower_gemm<128, false, false>, cudaFuncAttributeMaxDynamicSharedMemorySize, (int)GEMM_SMEM);
    cudaFuncSetAttribute(tower_gemm<16,  false, false>, cudaFuncAttributeMaxDynamicSharedMemorySize, (int)GEMM_SMEM);

    unsigned *l0, *l1, *l2, *f, *t1c, *t1r, *t2c, *t2r;
    float *sk1, *sk2;
    __nv_bfloat16 *whi, *wlo;
    cudaGetSymbolAddress((void**)&l0,  g_l0);
    cudaGetSymbolAddress((void**)&l1,  g_l1);
    cudaGetSymbolAddress((void**)&l2,  g_l2);
    cudaGetSymbolAddress((void**)&f,   g_f);
    cudaGetSymbolAddress((void**)&t1c, g_t1c);
    cudaGetSymbolAddress((void**)&t1r, g_t1r);
    cudaGetSymbolAddress((void**)&t2c, g_t2c);
    cudaGetSymbolAddress((void**)&t2r, g_t2r);
    cudaGetSymbolAddress((void**)&sk1, g_sk1);
    cudaGetSymbolAddress((void**)&sk2, g_sk2);
    cudaGetSymbolAddress((void**)&whi, g_whi);
    cudaGetSymbolAddress((void**)&wlo, g_wlo);

    // ---- merged weight pre-transform ----
    {
        WtTab T;
        const WtEnt ents[12] = {
            { lw0, WOFF_L0,  256, 512,  1 },
            { lw1, WOFF_L1,  256, 1024, 1 },
            { lw2, WOFF_L2,  256, 2048, 1 },
            { fw0, WOFF_FW0, 256, 256,  9 },
            { fw1, WOFF_FW1, 256, 256,  9 },
            { fw2, WOFF_FW2, 256, 256,  9 },
            { cw0, WOFF_CW0, 256, 256,  9 },
            { cw1, WOFF_CW1, 256, 256,  9 },
            { cw2, WOFF_CW2, 240, 256,  9 },
            { rw0, WOFF_RW0, 256, 256,  9 },
            { rw1, WOFF_RW1, 256, 256,  9 },
            { rw2, WOFF_RW2, 12,  256,  9 },
        };
        for (int i = 0; i < 12; ++i) T.e[i] = ents[i];
        wt_all<<<(unsigned)((WARENA + 255) / 256), 256>>>(T, whi, wlo);
    }

    // ---- FPN laterals ----
    lat_gemm<false><<<dim3(32, 2, 8), 256, GEMM_SMEM>>>(
        feat3, whi + WOFF_L0, wlo + WOFF_L0, lb0, l0, 512, 6, 0, 0);
    lat_gemm<true><<<dim3(8, 8, 8), 256, GEMM_SMEM>>>(
        feat4, whi + WOFF_L1, wlo + WOFF_L1, lb1, sk1, 1024, 5, 4, 8LL * 256 * 1024);
    lat_gemm<true><<<dim3(2, 16, 8), 256, GEMM_SMEM>>>(
        feat5, whi + WOFF_L2, wlo + WOFF_L2, lb2, sk2, 2048, 4, 4, 8LL * 256 * 256);
    {
        long long n1 = 8LL * 256 * 1024;
        red_kernel<<<(unsigned)((n1 + 255) / 256), 256>>>(sk1, l1, lb1, 4,
                                                          8LL * 256 * 1024, 10, n1);
        long long n2 = 8LL * 256 * 256;
        red_kernel<<<(unsigned)((n2 + 255) / 256), 256>>>(sk2, l2, lb2, 8,
                                                          8LL * 256 * 256, 8, n2);
    }

    // ---- top-down merge (packed) ----
    {
        long long n1 = 8LL * 256 * 32 * 32;
        up2add_kernel<<<(unsigned)((n1 + 255) / 256), 256>>>(l1, l2, 16, 16);
        long long n0 = 8LL * 256 * 64 * 64;
        up2add_kernel<<<(unsigned)((n0 + 255) / 256), 256>>>(l0, l1, 32, 32);
    }

    // ---- multi-level tower launches (grid.x = 42 covers all levels) ----
    const long long obI[3] = { 256LL * 4096, 256LL * 1024, 256LL * 256 };
    const long long ocI[3] = { 4096, 1024, 256 };
    const long long obF[3] = { 5376LL * 252, 5376LL * 252, 5376LL * 252 };
    const long long ocF[3] = { 1, 1, 1 };

    auto mkT = [&](const unsigned* i0, const unsigned* i1, const unsigned* i2,
                   void* o0, void* o1, void* o2,
                   long long w0, long long w1, long long w2,
                   const float* b0, const float* b1, const float* b2,
                   const long long* ob, const long long* oc, long long op) {
        TArgs T;
        T.in[0] = i0; T.in[1] = i1; T.in[2] = i2;
        T.out[0] = o0; T.out[1] = o1; T.out[2] = o2;
        T.wh[0] = whi + w0; T.wh[1] = whi + w1; T.wh[2] = whi + w2;
        T.wl[0] = wlo + w0; T.wl[1] = wlo + w1; T.wl[2] = wlo + w2;
        T.bias[0] = b0; T.bias[1] = b1; T.bias[2] = b2;
        for (int i = 0; i < 3; ++i) { T.ob[i] = ob[i]; T.oc[i] = oc[i]; }
        T.op = op;
        return T;
    };

    // FPN 3x3 output convs
    {
        TArgs T = mkT(l0, l1, l2, f, f + SEG1, f + SEG2,
                      WOFF_FW0, WOFF_FW1, WOFF_FW2, fb0, fb1, fb2, obI, ocI, 1);
        tower_gemm<128, false, true><<<dim3(42, 2, 8), 256, GEMM_SMEM>>>(T, 256);
    }
    // cls tower conv1/conv2
    {
        TArgs T = mkT(f, f + SEG1, f + SEG2, t1c, t1c + SEG1, t1c + SEG2,
                      WOFF_CW0, WOFF_CW0, WOFF_CW0, cb0, cb0, cb0, obI, ocI, 1);
        tower_gemm<128, true, true><<<dim3(42, 2, 8), 256, GEMM_SMEM>>>(T, 256);
    }
    {
        TArgs T = mkT(t1c, t1c + SEG1, t1c + SEG2, t2c, t2c + SEG1, t2c + SEG2,
                      WOFF_CW1, WOFF_CW1, WOFF_CW1, cb1, cb1, cb1, obI, ocI, 1);
        tower_gemm<128, true, true><<<dim3(42, 2, 8), 256, GEMM_SMEM>>>(T, 256);
    }
    // reg tower conv1/conv2
    {
        TArgs T = mkT(f, f + SEG1, f + SEG2, t1r, t1r + SEG1, t1r + SEG2,
                      WOFF_RW0, WOFF_RW0, WOFF_RW0, rb0, rb0, rb0, obI, ocI, 1);
        tower_gemm<128, true, true><<<dim3(42, 2, 8), 256, GEMM_SMEM>>>(T, 256);
    }
    {
        TArgs T = mkT(t1r, t1r + SEG1, t1r + SEG2, t2r, t2r + SEG1, t2r + SEG2,
                      WOFF_RW1, WOFF_RW1, WOFF_RW1, rb1, rb1, rb1, obI, ocI, 1);
        tower_gemm<128, true, true><<<dim3(42, 2, 8), 256, GEMM_SMEM>>>(T, 256);
    }
    // cls final -> d_out columns [0,240)
    {
        TArgs T = mkT(t2c, t2c + SEG1, t2c + SEG2,
                      out, out + 4096LL * 252, out + 5120LL * 252,
                      WOFF_CW2, WOFF_CW2, WOFF_CW2, cb2, cb2, cb2, obF, ocF, 252);
        tower_gemm<128, false, false><<<dim3(42, 2, 8), 256, GEMM_SMEM>>>(T, 240);
    }
    // reg final -> d_out columns [240,252)
    {
        TArgs T = mkT(t2r, t2r + SEG1, t2r + SEG2,
                      out + 240, out + 4096LL * 252 + 240, out + 5120LL * 252 + 240,
                      WOFF_RW2, WOFF_RW2, WOFF_RW2, rb2, rb2, rb2, obF, ocF, 252);
        tower_gemm<16, false, false><<<dim3(42, 1, 8), 256, GEMM_SMEM>>>(T, 12);
    }

    anchors_kernel<<<(16128 + 255) / 256, 256>>>(out + 10838016LL);
}

// round 6
// speedup vs baseline: 2.4007x; 1.5002x over previous
#include <cuda_runtime.h>
#include <cuda_bf16.h>
#include <cstdint>

// ---------------- packed bf16 hi/lo intermediates (u32 = lo16<<16 | hi16) ----
#define SEG1 8388608LL
#define SEG2 10485760LL
__device__ __align__(16) unsigned g_l0 [8 * 256 * 4096];
__device__ __align__(16) unsigned g_l1 [8 * 256 * 1024];
__device__ __align__(16) unsigned g_l2 [8 * 256 * 256];
__device__ __align__(16) unsigned g_f  [8 * 256 * 5376];
__device__ __align__(16) unsigned g_t1c[8 * 256 * 5376];
__device__ __align__(16) unsigned g_t1r[8 * 256 * 5376];
__device__ __align__(16) unsigned g_t2c[8 * 256 * 5376];
__device__ __align__(16) unsigned g_t2r[8 * 256 * 5376];
__device__ __align__(16) float g_sk1[4 * 8 * 256 * 1024];
__device__ __align__(16) float g_sk2[8 * 8 * 256 * 256];

// ---------------- bf16 hi/lo weight arena (t-major K layout) -----------------
#define WOFF_L0  0LL
#define WOFF_L1  131072LL
#define WOFF_L2  393216LL
#define WOFF_FW0 917504LL
#define WOFF_FW1 1507328LL
#define WOFF_FW2 2097152LL
#define WOFF_CW0 2686976LL
#define WOFF_CW1 3276800LL
#define WOFF_CW2 3866624LL
#define WOFF_RW0 4456448LL
#define WOFF_RW1 5046272LL
#define WOFF_RW2 5636096LL
#define WARENA   5672960LL
__device__ __nv_bfloat16 g_whi[WARENA];
__device__ __nv_bfloat16 g_wlo[WARENA];

// ---------------- helpers ----------------------------------------------------
#define SWZ(off)  ((off) ^ (((off) >> 3) & 0x70))   // 128B-row swizzle
#define SWZA(off) ((off) ^ (((off) >> 4) & 0x70))   // 256B-row swizzle

static __device__ __forceinline__ uint32_t smem_u32(const void* p) {
    uint32_t a;
    asm("{ .reg .u64 t; cvta.to.shared.u64 t, %1; cvt.u32.u64 %0, t; }"
        : "=r"(a) : "l"(p));
    return a;
}
static __device__ __forceinline__ uint32_t packf(float v) {
    uint32_t vb = __float_as_uint(v);
    uint32_t hb = (vb + 0x7FFFu + ((vb >> 16) & 1u)) & 0xFFFF0000u;
    float r = v - __uint_as_float(hb);
    uint32_t rb = __float_as_uint(r);
    uint32_t lb = (rb + 0x7FFFu + ((rb >> 16) & 1u)) & 0xFFFF0000u;
    return (hb >> 16) | lb;
}
static __device__ __forceinline__ float unpackf(uint32_t p) {
    return __uint_as_float(p << 16) + __uint_as_float(p & 0xFFFF0000u);
}

#define LDSM_X4(r0, r1, r2, r3, ad) \
    asm volatile("ldmatrix.sync.aligned.m8n8.x4.shared.b16 {%0,%1,%2,%3}, [%4];" \
                 : "=r"(r0), "=r"(r1), "=r"(r2), "=r"(r3) : "r"(ad))
#define LDSM_X4T(r0, r1, r2, r3, ad) \
    asm volatile("ldmatrix.sync.aligned.m8n8.x4.trans.shared.b16 {%0,%1,%2,%3}, [%4];" \
                 : "=r"(r0), "=r"(r1), "=r"(r2), "=r"(r3) : "r"(ad))
#define LDSM_X2(r0, r1, ad) \
    asm volatile("ldmatrix.sync.aligned.m8n8.x2.shared.b16 {%0,%1}, [%2];" \
                 : "=r"(r0), "=r"(r1) : "r"(ad))
#define MMA16816(d, a, b) \
    asm volatile("mma.sync.aligned.m16n8k16.row.col.f32.bf16.bf16.f32 " \
                 "{%0,%1,%2,%3},{%4,%5,%6,%7},{%8,%9},{%0,%1,%2,%3};" \
                 : "+f"((d)[0]), "+f"((d)[1]), "+f"((d)[2]), "+f"((d)[3]) \
                 : "r"((a)[0]), "r"((a)[1]), "r"((a)[2]), "r"((a)[3]), \
                   "r"((b)[0]), "r"((b)[1]))
#define CVT2BF(dst, hi, lo) \
    asm("cvt.rn.bf16x2.f32 %0, %1, %2;" : "=r"(dst) : "f"(hi), "f"(lo))

// ---------------- merged weight pre-transform --------------------------------
struct WtEnt { const float* src; long long start; int coutA; int cin; int taps; };
struct WtTab { WtEnt e[12]; };

__global__ void wt_all(WtTab T, __nv_bfloat16* __restrict__ hi,
                       __nv_bfloat16* __restrict__ lo)
{
    long long idx = (long long)blockIdx.x * 256 + threadIdx.x;
    if (idx >= WARENA) return;
    int i = 0;
#pragma unroll
    for (int j = 1; j < 12; ++j) if (idx >= T.e[j].start) i = j;
    const WtEnt E = T.e[i];
    long long local = idx - E.start;
    const int Kk = E.cin * E.taps;
    long long co = local / Kk;
    int r  = (int)(local - co * Kk);
    int t  = r / E.cin;
    int ci = r - t * E.cin;
    float v = 0.f;
    if (co < E.coutA) v = E.src[co * Kk + (long long)ci * E.taps + t];
    __nv_bfloat16 h = __float2bfloat16(v);
    float rr = v - __bfloat162float(h);
    hi[idx] = h;
    lo[idx] = __float2bfloat16(rr);
}

// ---------------- lateral 1x1 GEMM (fp32 in, [k][px]+trans path) -------------
template <int N8T>
static __device__ __forceinline__ void mma_chunk(
    uint32_t aHI, uint32_t aLO, uint32_t bHI, uint32_t bLO,
    float (&acc)[2][N8T][4], int m_base, int n_base, int g, int lr)
{
#pragma unroll
    for (int s = 0; s < 4; ++s) {
        uint32_t bh[N8T][2];
#pragma unroll
        for (int np = 0; np < N8T / 2; ++np) {
            int nrow = n_base + np * 16 + (g >> 1) * 8 + lr;
            uint32_t ad = bHI + SWZ((uint32_t)(nrow * 128 + s * 32 + (g & 1) * 16));
            LDSM_X4(bh[np*2][0], bh[np*2][1], bh[np*2+1][0], bh[np*2+1][1], ad);
        }
        uint32_t ah[2][4];
#pragma unroll
        for (int mt = 0; mt < 2; ++mt) {
            int krow = s * 16 + (g >> 1) * 8 + lr;
            int colb = (m_base + mt * 16 + (g & 1) * 8) * 2;
            uint32_t ad = aHI + SWZA((uint32_t)(krow * 256 + colb));
            LDSM_X4T(ah[mt][0], ah[mt][1], ah[mt][2], ah[mt][3], ad);
        }
#pragma unroll
        for (int mt = 0; mt < 2; ++mt)
#pragma unroll
            for (int nt = 0; nt < N8T; ++nt)
                MMA16816(acc[mt][nt], ah[mt], bh[nt]);

        uint32_t al[2][4];
#pragma unroll
        for (int mt = 0; mt < 2; ++mt) {
            int krow = s * 16 + (g >> 1) * 8 + lr;
            int colb = (m_base + mt * 16 + (g & 1) * 8) * 2;
            uint32_t ad = aLO + SWZA((uint32_t)(krow * 256 + colb));
            LDSM_X4T(al[mt][0], al[mt][1], al[mt][2], al[mt][3], ad);
        }
#pragma unroll
        for (int mt = 0; mt < 2; ++mt)
#pragma unroll
            for (int nt = 0; nt < N8T; ++nt)
                MMA16816(acc[mt][nt], al[mt], bh[nt]);

        uint32_t bl[N8T][2];
#pragma unroll
        for (int np = 0; np < N8T / 2; ++np) {
            int nrow = n_base + np * 16 + (g >> 1) * 8 + lr;
            uint32_t ad = bLO + SWZ((uint32_t)(nrow * 128 + s * 32 + (g & 1) * 16));
            LDSM_X4(bl[np*2][0], bl[np*2][1], bl[np*2+1][0], bl[np*2+1][1], ad);
        }
#pragma unroll
        for (int mt = 0; mt < 2; ++mt)
#pragma unroll
            for (int nt = 0; nt < N8T; ++nt)
                MMA16816(acc[mt][nt], ah[mt], bl[nt]);
    }
}

template <bool SPLIT>
__global__ void __launch_bounds__(256, 2)
lat_gemm(const float* __restrict__ in, const __nv_bfloat16* __restrict__ wh,
         const __nv_bfloat16* __restrict__ wl, const float* __restrict__ bias,
         void* outv, int Cin, int logW, int chunksPer, long long sliceStride)
{
    extern __shared__ char dsm[];
    const int tid = threadIdx.x;
    uint32_t u0  = smem_u32(dsm);
    uint32_t pad = (1024u - (u0 & 1023u)) & 1023u;
    char*    db  = dsm + pad;
    uint32_t dyn = u0 + pad;

    const int yb = blockIdx.y;
    const int coTile = yb & 1, slice = yb >> 1;
    const int HW = 1 << (2 * logW);
    const int co0 = coTile * 128;
    const int bz  = blockIdx.z;
    const int p0  = blockIdx.x * 128;
    const int c0  = SPLIT ? slice * chunksPer : 0;
    const int nch = SPLIT ? chunksPer : (Cin >> 6);
    const int K   = Cin;

    const int wid = tid >> 5, lane = tid & 31;
    const int m_base = (wid & 3) * 32;
    const int n_base = (wid >> 2) * 64;
    const int g = lane >> 3, lr = lane & 7;

    const uint32_t aHI = dyn, aLO = dyn + 16384;
    const uint32_t bHI = dyn + 32768, bLO = dyn + 49152;

    float acc[2][8][4];
#pragma unroll
    for (int mt = 0; mt < 2; ++mt)
#pragma unroll
        for (int nt = 0; nt < 8; ++nt)
#pragma unroll
            for (int r = 0; r < 4; ++r) acc[mt][nt][r] = 0.f;

    for (int cc = 0; cc < nch; ++cc) {
        const int k0 = (c0 + cc) << 6;
#pragma unroll
        for (int j = 0; j < 8; ++j) {
            int idx = tid + j * 256;
            int k = idx >> 5, q = idx & 31;
            const float4 f4 = *(const float4*)(in +
                ((long long)(bz * Cin + k0 + k)) * HW + p0 + q * 4);
            float v0 = f4.x, v1 = f4.y, v2 = f4.z, v3 = f4.w;
            uint32_t h01, h23, l01, l23;
            CVT2BF(h01, v1, v0);
            CVT2BF(h23, v3, v2);
            float r0 = v0 - __uint_as_float((h01 & 0xFFFFu) << 16);
            float r1 = v1 - __uint_as_float(h01 & 0xFFFF0000u);
            float r2 = v2 - __uint_as_float((h23 & 0xFFFFu) << 16);
            float r3 = v3 - __uint_as_float(h23 & 0xFFFF0000u);
            CVT2BF(l01, r1, r0);
            CVT2BF(l23, r3, r2);
            uint32_t off = SWZA((uint32_t)k * 256u + (uint32_t)q * 8u);
            *(uint2*)(db + off)         = make_uint2(h01, h23);
            *(uint2*)(db + 16384 + off) = make_uint2(l01, l23);
        }
        {
            const char* sH = (const char*)(wh + (long long)co0 * K + k0);
            const char* sL = (const char*)(wl + (long long)co0 * K + k0);
            const long long rowb = (long long)K * 2;
#pragma unroll
            for (int j = 0; j < 4; ++j) {
                int idx = tid + j * 256;
                int r = idx >> 3, c = idx & 7;
                uint4 hv = *(const uint4*)(sH + r * rowb + c * 16);
                uint4 lv = *(const uint4*)(sL + r * rowb + c * 16);
                uint32_t off = SWZ((uint32_t)r * 128u + (uint32_t)c * 16u);
                *(uint4*)(db + 32768 + off) = hv;
                *(uint4*)(db + 49152 + off) = lv;
            }
        }
        __syncthreads();
        mma_chunk<8>(aHI, aLO, bHI, bLO, acc, m_base, n_base, g, lr);
        __syncthreads();
    }

#pragma unroll
    for (int mt = 0; mt < 2; ++mt)
#pragma unroll
        for (int nt = 0; nt < 8; ++nt)
#pragma unroll
            for (int rg = 0; rg < 4; ++rg) {
                int m  = m_base + mt * 16 + (lane >> 2) + ((rg >= 2) ? 8 : 0);
                int co = co0 + n_base + nt * 8 + (lane & 3) * 2 + (rg & 1);
                long long off = ((long long)(bz * 256 + co)) * HW + p0 + m;
                if (SPLIT) {
                    ((float*)outv)[slice * sliceStride + off] = acc[mt][nt][rg];
                } else {
                    ((unsigned*)outv)[off] = packf(acc[mt][nt][rg] + bias[co]);
                }
            }
}

// ---------------- split-K reduce (+bias, pack) --------------------------------
__global__ void red_kernel(const float* __restrict__ src, unsigned* __restrict__ dst,
                           const float* __restrict__ bias, int slices,
                           long long sliceStride, int logHW, long long n)
{
    long long idx = (long long)blockIdx.x * 256 + threadIdx.x;
    if (idx >= n) return;
    float v = bias[(int)((idx >> logHW) & 255)];
    for (int s = 0; s < slices; ++s) v += src[s * sliceStride + idx];
    dst[idx] = packf(v);
}

// ---------------- 3x3 tower GEMM: halo-A tile, taps via row-shifted ldmatrix --
struct TArgs {
    const unsigned* in[6];
    void* out[6];
    const __nv_bfloat16* wh[6];
    const __nv_bfloat16* wl[6];
    const float* bias[6];
    long long ob[6];
    long long oc[6];
    long long op;
};

#define A_HI 0u
#define A_LO 34816u
#define B_HI 69632u
#define B_LO 86016u
#define TOWER_DYN 102400

template <int NTILE, bool RELU, bool OUTP>
__global__ void __launch_bounds__(256, 2)
tower_gemm(TArgs T, int CoutActual)
{
    extern __shared__ char dsm[];
    const int tid = threadIdx.x;
    uint32_t u0  = smem_u32(dsm);
    uint32_t padB = (1024u - (u0 & 1023u)) & 1023u;
    char*    db  = dsm + padB;
    uint32_t dyn = u0 + padB;

    const int xb  = blockIdx.x;
    const int lvl = (xb >= 40) ? 2 : ((xb >= 32) ? 1 : 0);
    const int xl  = xb - ((lvl == 2) ? 40 : ((lvl == 1) ? 32 : 0));
    const int logW = 6 - lvl;
    const int W    = 1 << logW;
    const int padW = W + 2;
    const int imgR = (128 >> logW) + 2;
    const int Rows = imgR * padW;            // 264 / 204 / 180
    const int RowsPad = (Rows + 15) & ~15;
    const int itersA = RowsPad >> 4;

    const int set    = blockIdx.y >> 1;
    const int coTile = blockIdx.y & 1;
    const int idx6   = set * 3 + lvl;

    const unsigned* __restrict__ in = T.in[idx6];
    const __nv_bfloat16* wh = T.wh[idx6];
    const __nv_bfloat16* wl = T.wl[idx6];
    const float* bias = T.bias[idx6];

    const int bz  = blockIdx.z;
    const int p0  = xl * 128;
    const int y0  = p0 >> logW;
    const int HW  = 1 << (2 * logW);
    const int co0 = coTile * NTILE;
    constexpr int K = 2304;

    constexpr int WN  = NTILE / 2;
    constexpr int N8T = WN / 8;
    const int wid = tid >> 5, lane = tid & 31;
    const int m_base = (wid & 3) * 32;
    const int n_base = (wid >> 2) * WN;
    const int g = lane >> 3, lr = lane & 7;

    float acc[2][N8T][4];
#pragma unroll
    for (int mt = 0; mt < 2; ++mt)
#pragma unroll
        for (int nt = 0; nt < N8T; ++nt)
#pragma unroll
            for (int r = 0; r < 4; ++r) acc[mt][nt][r] = 0.f;

    for (int cic = 0; cic < 4; ++cic) {
        // ---- stage A halo tile once per 64-ci chunk: rows [pad px][64 ci] ----
        for (int i = 0; i < itersA; ++i) {
            int e = tid + i * 256;
            int j = e / RowsPad;            // ci quad 0..15
            int r = e - j * RowsPad;        // padded row
            int iy = r / padW;
            int ix = r - iy * padW;
            int yi = y0 - 1 + iy;
            int xv = ix - 1;
            bool ok = (r < Rows) && ((unsigned)yi < (unsigned)W) &&
                      ((unsigned)xv < (unsigned)W);
            uint32_t v[4];
            const long long base =
                ((long long)(bz * 256 + cic * 64 + j * 4)) * HW + yi * W + xv;
#pragma unroll
            for (int jj = 0; jj < 4; ++jj)
                v[jj] = ok ? __ldg(in + base + (long long)jj * HW) : 0u;
            uint32_t h01 = __byte_perm(v[0], v[1], 0x5410);
            uint32_t h23 = __byte_perm(v[2], v[3], 0x5410);
            uint32_t l01 = __byte_perm(v[0], v[1], 0x7632);
            uint32_t l23 = __byte_perm(v[2], v[3], 0x7632);
            uint32_t off = SWZ((uint32_t)r * 128u + (uint32_t)j * 8u);
            *(uint2*)(db + A_HI + off) = make_uint2(h01, h23);
            *(uint2*)(db + A_LO + off) = make_uint2(l01, l23);
        }
        __syncthreads();

        for (int t = 0; t < 9; ++t) {
            const int dy = t / 3 - 1;
            const int dx = t - (t / 3) * 3 - 1;
            const int k0 = t * 256 + cic * 64;

            // ---- stage B [NTILE rows][64 k] ----
            {
                const char* sH = (const char*)(wh + (long long)co0 * K + k0);
                const char* sL = (const char*)(wl + (long long)co0 * K + k0);
                const long long rowb = (long long)K * 2;
#pragma unroll
                for (int j = 0; j < (NTILE * 8 + 255) / 256; ++j) {
                    int idx = tid + j * 256;
                    if (idx < NTILE * 8) {
                        int r = idx >> 3, c = idx & 7;
                        uint4 hv = *(const uint4*)(sH + r * rowb + c * 16);
                        uint4 lv = *(const uint4*)(sL + r * rowb + c * 16);
                        uint32_t off = SWZ((uint32_t)r * 128u + (uint32_t)c * 16u);
                        *(uint4*)(db + B_HI + off) = hv;
                        *(uint4*)(db + B_LO + off) = lv;
                    }
                }
            }
            __syncthreads();

            // ---- MMA: A rows selected by tap shift ----
            int prow[2];
#pragma unroll
            for (int mt = 0; mt < 2; ++mt) {
                int m = m_base + mt * 16 + ((g & 1) << 3) + lr;
                prow[mt] = (1 + (m >> logW) + dy) * padW + (m & (W - 1)) + 1 + dx;
            }
            const int colA0 = (g >> 1) * 16;

#pragma unroll
            for (int s = 0; s < 4; ++s) {
                uint32_t bh[N8T][2];
                if constexpr (N8T == 1) {
                    uint32_t ad = dyn + B_HI +
                        SWZ((uint32_t)((n_base + lr) * 128 + s * 32 + (g & 1) * 16));
                    LDSM_X2(bh[0][0], bh[0][1], ad);
                } else {
#pragma unroll
                    for (int np = 0; np < N8T / 2; ++np) {
                        int nrow = n_base + np * 16 + (g >> 1) * 8 + lr;
                        uint32_t ad = dyn + B_HI +
                            SWZ((uint32_t)(nrow * 128 + s * 32 + (g & 1) * 16));
                        LDSM_X4(bh[np*2][0], bh[np*2][1], bh[np*2+1][0], bh[np*2+1][1], ad);
                    }
                }
                uint32_t ah[2][4];
#pragma unroll
                for (int mt = 0; mt < 2; ++mt) {
                    uint32_t ad = dyn + A_HI +
                        SWZ((uint32_t)(prow[mt] * 128 + s * 32 + colA0));
                    LDSM_X4(ah[mt][0], ah[mt][1], ah[mt][2], ah[mt][3], ad);
                }
#pragma unroll
                for (int mt = 0; mt < 2; ++mt)
#pragma unroll
                    for (int nt = 0; nt < N8T; ++nt)
                        MMA16816(acc[mt][nt], ah[mt], bh[nt]);

                uint32_t al[2][4];
#pragma unroll
                for (int mt = 0; mt < 2; ++mt) {
                    uint32_t ad = dyn + A_LO +
                        SWZ((uint32_t)(prow[mt] * 128 + s * 32 + colA0));
                    LDSM_X4(al[mt][0], al[mt][1], al[mt][2], al[mt][3], ad);
                }
#pragma unroll
                for (int mt = 0; mt < 2; ++mt)
#pragma unroll
                    for (int nt = 0; nt < N8T; ++nt)
                        MMA16816(acc[mt][nt], al[mt], bh[nt]);

                uint32_t bl[N8T][2];
                if constexpr (N8T == 1) {
                    uint32_t ad = dyn + B_LO +
                        SWZ((uint32_t)((n_base + lr) * 128 + s * 32 + (g & 1) * 16));
                    LDSM_X2(bl[0][0], bl[0][1], ad);
                } else {
#pragma unroll
                    for (int np = 0; np < N8T / 2; ++np) {
                        int nrow = n_base + np * 16 + (g >> 1) * 8 + lr;
                        uint32_t ad = dyn + B_LO +
                            SWZ((uint32_t)(nrow * 128 + s * 32 + (g & 1) * 16));
                        LDSM_X4(bl[np*2][0], bl[np*2][1], bl[np*2+1][0], bl[np*2+1][1], ad);
                    }
                }
#pragma unroll
                for (int mt = 0; mt < 2; ++mt)
#pragma unroll
                    for (int nt = 0; nt < N8T; ++nt)
                        MMA16816(acc[mt][nt], ah[mt], bl[nt]);
            }
            __syncthreads();
        }
    }

    // ---- epilogue ----
    const long long obase = (long long)bz * T.ob[idx6];
    const long long oc = T.oc[idx6];
    const long long op = T.op;
#pragma unroll
    for (int mt = 0; mt < 2; ++mt)
#pragma unroll
        for (int nt = 0; nt < N8T; ++nt)
#pragma unroll
            for (int rg = 0; rg < 4; ++rg) {
                int m  = m_base + mt * 16 + (lane >> 2) + ((rg >= 2) ? 8 : 0);
                int co = co0 + n_base + nt * 8 + (lane & 3) * 2 + (rg & 1);
                if (co < CoutActual) {
                    float v = acc[mt][nt][rg] + bias[co];
                    if (RELU) v = fmaxf(v, 0.f);
                    long long off = obase + (long long)co * oc + (long long)(p0 + m) * op;
                    if (OUTP) ((unsigned*)T.out[idx6])[off] = packf(v);
                    else      ((float*)T.out[idx6])[off]    = v;
                }
            }
}

// ---------------- nearest 2x upsample + add (packed domain) ------------------
__global__ void up2add_kernel(unsigned* __restrict__ big,
                              const unsigned* __restrict__ small, int Hs, int Ws)
{
    const int H = Hs * 2, W = Ws * 2;
    const long long total = 8LL * 256 * H * W;
    long long idx = (long long)blockIdx.x * blockDim.x + threadIdx.x;
    if (idx >= total) return;
    int x = (int)(idx % W);
    int y = (int)((idx / W) % H);
    long long bc = idx / ((long long)W * H);
    float v = unpackf(big[idx]) + unpackf(small[(bc * Hs + (y >> 1)) * Ws + (x >> 1)]);
    big[idx] = packf(v);
}

// ---------------- anchors ----------------------------------------------------
__global__ void anchors_kernel(float* __restrict__ out)
{
    int i = blockIdx.x * blockDim.x + threadIdx.x;
    if (i >= 16128) return;
    int lvl, rem;
    if (i < 12288)      { lvl = 0; rem = i; }
    else if (i < 15360) { lvl = 1; rem = i - 12288; }
    else                { lvl = 2; rem = i - 15360; }
    const int w        = 64 >> lvl;
    const float stride = 8.0f * (float)(1 << lvl);
    const float bs     = 32.0f * (float)(1 << lvl);
    const int a = rem % 3;
    const int s = rem / 3;
    const int x = s % w;
    const int y = s / w;
    const float sq[3] = {0.70710678118654752f, 1.0f, 1.41421356237309505f};
    const float hw = bs * sq[a] * 0.5f;
    const float hh = bs / sq[a] * 0.5f;
    const float cx = (float)x * stride;
    const float cy = (float)y * stride;
    float* o = out + (long long)i * 4;
    o[0] = cx - hw; o[1] = cy - hh; o[2] = cx + hw; o[3] = cy + hh;
}

// ---------------- host dispatch ----------------------------------------------
static const size_t LAT_SMEM   = 66560;
static const size_t TOWER_SMEM = TOWER_DYN + 1024;

extern "C" void kernel_launch(void* const* d_in, const int* in_sizes, int n_in,
                              void* d_out, int out_size)
{
    const float* feat3 = (const float*)d_in[0];
    const float* feat4 = (const float*)d_in[1];
    const float* feat5 = (const float*)d_in[2];
    const float* lw0 = (const float*)d_in[3];  const float* lb0 = (const float*)d_in[4];
    const float* lw1 = (const float*)d_in[5];  const float* lb1 = (const float*)d_in[6];
    const float* lw2 = (const float*)d_in[7];  const float* lb2 = (const float*)d_in[8];
    const float* fw0 = (const float*)d_in[9];  const float* fb0 = (const float*)d_in[10];
    const float* fw1 = (const float*)d_in[11]; const float* fb1 = (const float*)d_in[12];
    const float* fw2 = (const float*)d_in[13]; const float* fb2 = (const float*)d_in[14];
    const float* cw0 = (const float*)d_in[15]; const float* cb0 = (const float*)d_in[16];
    const float* cw1 = (const float*)d_in[17]; const float* cb1 = (const float*)d_in[18];
    const float* cw2 = (const float*)d_in[19]; const float* cb2 = (const float*)d_in[20];
    const float* rw0 = (const float*)d_in[21]; const float* rb0 = (const float*)d_in[22];
    const float* rw1 = (const float*)d_in[23]; const float* rb1 = (const float*)d_in[24];
    const float* rw2 = (const float*)d_in[25]; const float* rb2 = (const float*)d_in[26];
    float* out = (float*)d_out;

    cudaFuncSetAttribute(lat_gemm<false>, cudaFuncAttributeMaxDynamicSharedMemorySize, (int)LAT_SMEM);
    cudaFuncSetAttribute(lat_gemm<true>,  cudaFuncAttributeMaxDynamicSharedMemorySize, (int)LAT_SMEM);
    cudaFuncSetAttribute(tower_gemm<128, false, true>,  cudaFuncAttributeMaxDynamicSharedMemorySize, (int)TOWER_SMEM);
    cudaFuncSetAttribute(tower_gemm<128, true,  true>,  cudaFuncAttributeMaxDynamicSharedMemorySize, (int)TOWER_SMEM);
    cudaFuncSetAttribute(tower_gemm<128, false, false>, cudaFuncAttributeMaxDynamicSharedMemorySize, (int)TOWER_SMEM);
    cudaFuncSetAttribute(tower_gemm<16,  false, false>, cudaFuncAttributeMaxDynamicSharedMemorySize, (int)TOWER_SMEM);

    unsigned *l0, *l1, *l2, *f, *t1c, *t1r, *t2c, *t2r;
    float *sk1, *sk2;
    __nv_bfloat16 *whi, *wlo;
    cudaGetSymbolAddress((void**)&l0,  g_l0);
    cudaGetSymbolAddress((void**)&l1,  g_l1);
    cudaGetSymbolAddress((void**)&l2,  g_l2);
    cudaGetSymbolAddress((void**)&f,   g_f);
    cudaGetSymbolAddress((void**)&t1c, g_t1c);
    cudaGetSymbolAddress((void**)&t1r, g_t1r);
    cudaGetSymbolAddress((void**)&t2c, g_t2c);
    cudaGetSymbolAddress((void**)&t2r, g_t2r);
    cudaGetSymbolAddress((void**)&sk1, g_sk1);
    cudaGetSymbolAddress((void**)&sk2, g_sk2);
    cudaGetSymbolAddress((void**)&whi, g_whi);
    cudaGetSymbolAddress((void**)&wlo, g_wlo);

    {
        WtTab T;
        const WtEnt ents[12] = {
            { lw0, WOFF_L0,  256, 512,  1 },
            { lw1, WOFF_L1,  256, 1024, 1 },
            { lw2, WOFF_L2,  256, 2048, 1 },
            { fw0, WOFF_FW0, 256, 256,  9 },
            { fw1, WOFF_FW1, 256, 256,  9 },
            { fw2, WOFF_FW2, 256, 256,  9 },
            { cw0, WOFF_CW0, 256, 256,  9 },
            { cw1, WOFF_CW1, 256, 256,  9 },
            { cw2, WOFF_CW2, 240, 256,  9 },
            { rw0, WOFF_RW0, 256, 256,  9 },
            { rw1, WOFF_RW1, 256, 256,  9 },
            { rw2, WOFF_RW2, 12,  256,  9 },
        };
        for (int i = 0; i < 12; ++i) T.e[i] = ents[i];
        wt_all<<<(unsigned)((WARENA + 255) / 256), 256>>>(T, whi, wlo);
    }

    // ---- FPN laterals ----
    lat_gemm<false><<<dim3(32, 2, 8), 256, LAT_SMEM>>>(
        feat3, whi + WOFF_L0, wlo + WOFF_L0, lb0, l0, 512, 6, 0, 0);
    lat_gemm<true><<<dim3(8, 8, 8), 256, LAT_SMEM>>>(
        feat4, whi + WOFF_L1, wlo + WOFF_L1, lb1, sk1, 1024, 5, 4, 8LL * 256 * 1024);
    lat_gemm<true><<<dim3(2, 16, 8), 256, LAT_SMEM>>>(
        feat5, whi + WOFF_L2, wlo + WOFF_L2, lb2, sk2, 2048, 4, 4, 8LL * 256 * 256);
    {
        long long n1 = 8LL * 256 * 1024;
        red_kernel<<<(unsigned)((n1 + 255) / 256), 256>>>(sk1, l1, lb1, 4,
                                                          8LL * 256 * 1024, 10, n1);
        long long n2 = 8LL * 256 * 256;
        red_kernel<<<(unsigned)((n2 + 255) / 256), 256>>>(sk2, l2, lb2, 8,
                                                          8LL * 256 * 256, 8, n2);
    }
    {
        long long n1 = 8LL * 256 * 32 * 32;
        up2add_kernel<<<(unsigned)((n1 + 255) / 256), 256>>>(l1, l2, 16, 16);
        long long n0 = 8LL * 256 * 64 * 64;
        up2add_kernel<<<(unsigned)((n0 + 255) / 256), 256>>>(l0, l1, 32, 32);
    }

    const long long obI[3] = { 256LL * 4096, 256LL * 1024, 256LL * 256 };
    const long long ocI[3] = { 4096, 1024, 256 };

    auto setSlot = [&](TArgs& T, int s, const unsigned* i0, const unsigned* i1,
                       const unsigned* i2, void* o0, void* o1, void* o2,
                       long long woff, const float* b, bool inter) {
        T.in[s*3+0] = i0; T.in[s*3+1] = i1; T.in[s*3+2] = i2;
        T.out[s*3+0] = o0; T.out[s*3+1] = o1; T.out[s*3+2] = o2;
        for (int l = 0; l < 3; ++l) {
            T.wh[s*3+l] = whi + woff;
            T.wl[s*3+l] = wlo + woff;
            T.bias[s*3+l] = b;
            T.ob[s*3+l] = inter ? obI[l] : 5376LL * 252;
            T.oc[s*3+l] = inter ? ocI[l] : 1;
        }
    };

    // FPN 3x3 output convs (per-level weights -> use slot machinery manually)
    {
        TArgs T;
        T.in[0] = l0; T.in[1] = l1; T.in[2] = l2;
        T.out[0] = f; T.out[1] = f + SEG1; T.out[2] = f + SEG2;
        const long long wo[3] = { WOFF_FW0, WOFF_FW1, WOFF_FW2 };
        const float* bb[3] = { fb0, fb1, fb2 };
        for (int l = 0; l < 3; ++l) {
            T.wh[l] = whi + wo[l]; T.wl[l] = wlo + wo[l]; T.bias[l] = bb[l];
            T.ob[l] = obI[l]; T.oc[l] = ocI[l];
        }
        T.op = 1;
        tower_gemm<128, false, true><<<dim3(42, 2, 8), 256, TOWER_SMEM>>>(T, 256);
    }
    // conv1 fused (cls set 0, reg set 1)
    {
        TArgs T; T.op = 1;
        setSlot(T, 0, f, f + SEG1, f + SEG2, t1c, t1c + SEG1, t1c + SEG2, WOFF_CW0, cb0, true);
        setSlot(T, 1, f, f + SEG1, f + SEG2, t1r, t1r + SEG1, t1r + SEG2, WOFF_RW0, rb0, true);
        tower_gemm<128, true, true><<<dim3(42, 4, 8), 256, TOWER_SMEM>>>(T, 256);
    }
    // conv2 fused
    {
        TArgs T; T.op = 1;
        setSlot(T, 0, t1c, t1c + SEG1, t1c + SEG2, t2c, t2c + SEG1, t2c + SEG2, WOFF_CW1, cb1, true);
        setSlot(T, 1, t1r, t1r + SEG1, t1r + SEG2, t2r, t2r + SEG1, t2r + SEG2, WOFF_RW1, rb1, true);
        tower_gemm<128, true, true><<<dim3(42, 4, 8), 256, TOWER_SMEM>>>(T, 256);
    }
    // cls final -> d_out cols [0,240)
    {
        TArgs T; T.op = 252;
        setSlot(T, 0, t2c, t2c + SEG1, t2c + SEG2,
                out, out + 4096LL * 252, out + 5120LL * 252, WOFF_CW2, cb2, false);
        tower_gemm<128, false, false><<<dim3(42, 2, 8), 256, TOWER_SMEM>>>(T, 240);
    }
    // reg final -> d_out cols [240,252)
    {
        TArgs T; T.op = 252;
        setSlot(T, 0, t2r, t2r + SEG1, t2r + SEG2,
                out + 240, out + 4096LL * 252 + 240, out + 5120LL * 252 + 240,
                WOFF_RW2, rb2, false);
        tower_gemm<16, false, false><<<dim3(42, 1, 8), 256, TOWER_SMEM>>>(T, 12);
    }

    anchors_kernel<<<(16128 + 255) / 256, 256>>>(out + 10838016LL);
}